// round 4
// baseline (speedup 1.0000x reference)
#include <cuda_runtime.h>
#include <math.h>

#define NN 20000
#define NE 640000
#define D  128
#define TE 32
#define TN 32
#define LDE 36   // [k][edge] row stride: 144B -> 16B aligned rows

typedef unsigned long long u64;

// ---------------- scratch (static device memory; no allocations) ----------------
__device__ float g_hh[NN * D];
__device__ float g_agg[NN * D];
__device__ float g_aggx[NN * 3];
__device__ float g_e3[NE * 3];
// duplicated weights: Wd[k][2c] = Wd[k][2c+1] = W[k][c]; rows K..Kp-1 zero
__device__ __align__(16) float g_Wa1d[260 * 256];
__device__ __align__(16) float g_We1d[132 * 256];
__device__ __align__(16) float g_We2d[128 * 256];
__device__ __align__(16) float g_Wc1d[260 * 256];
__device__ __align__(16) float g_Wc2d[128 * 256];

__device__ __forceinline__ float siluf(float v) { return v / (1.f + expf(-v)); }

// ---------------- packed f32x2 primitives ----------------
__device__ __forceinline__ u64 ffma2(u64 a, u64 b, u64 c) {
    u64 d;
    asm("fma.rn.f32x2 %0, %1, %2, %3;" : "=l"(d) : "l"(a), "l"(b), "l"(c));
    return d;
}
__device__ __forceinline__ u64 dup2(float w) {
    u64 d;
    asm("mov.b64 %0, {%1, %1};" : "=l"(d) : "f"(w));
    return d;
}
__device__ __forceinline__ float2 unpk(u64 a) {
    float2 r;
    asm("mov.b64 {%0, %1}, %2;" : "=f"(r.x), "=f"(r.y) : "l"(a));
    return r;
}
__device__ __forceinline__ void red4(float* p, float a, float b, float c, float d) {
    asm volatile("red.global.add.v4.f32 [%0], {%1, %2, %3, %4};"
                 :: "l"(p), "f"(a), "f"(b), "f"(c), "f"(d) : "memory");
}
__device__ __forceinline__ void silu_store2(float* dst, u64 a) {
    float2 v = unpk(a);
    float2 r;
    r.x = siluf(v.x);
    r.y = siluf(v.y);
    *(float2*)dst = r;
}

// ---------------- weight dup-copy ----------------
__global__ void prep_weights(const float* __restrict__ Wa1, const float* __restrict__ We1,
                             const float* __restrict__ We2, const float* __restrict__ Wc1,
                             const float* __restrict__ Wc2) {
    int m = blockIdx.y;
    const float* src; float* dst; int K, Kp;
    if (m == 0)      { src = Wa1; dst = g_Wa1d; K = 259; Kp = 260; }
    else if (m == 1) { src = We1; dst = g_We1d; K = 131; Kp = 132; }
    else if (m == 2) { src = We2; dst = g_We2d; K = 128; Kp = 128; }
    else if (m == 3) { src = Wc1; dst = g_Wc1d; K = 259; Kp = 260; }
    else             { src = Wc2; dst = g_Wc2d; K = 128; Kp = 128; }
    int total = Kp * 128;
    for (int idx = blockIdx.x * blockDim.x + threadIdx.x; idx < total;
         idx += gridDim.x * blockDim.x) {
        int k = idx >> 7, c = idx & 127;
        float v = (k < K) ? src[idx] : 0.f;
        dst[k * 256 + 2 * c]     = v;
        dst[k * 256 + 2 * c + 1] = v;
    }
}

__global__ void zero_scratch() {
    int idx = blockIdx.x * blockDim.x + threadIdx.x;
    int stride = gridDim.x * blockDim.x;
    for (int i = idx; i < NN * D; i += stride) g_agg[i] = 0.f;
    for (int i = idx; i < NN * 3; i += stride) g_aggx[i] = 0.f;
}

// ---------------- tiled packed GEMM core ----------------
// s_in: [K][LDE] (edge contiguous). Thread computes 4 cols (c0..c0+3) x 8 edges
// (e0..e0+7) as acc[c*4+p] = f32x2 over edge pairs. Per k: 2 LDS.128 (A) +
// 2 LDG.128 (dup weights) + 16 FFMA2 -> FMA-pipe bound.
template <int K>
__device__ __forceinline__ void mlp2t(const float* __restrict__ Wd, const float* s_in,
                                      const float* __restrict__ bias,
                                      u64* acc, int c0, int e0) {
#pragma unroll
    for (int c = 0; c < 4; c++) {
        u64 b2 = dup2(bias[c0 + c]);
#pragma unroll
        for (int p = 0; p < 4; p++) acc[c * 4 + p] = b2;
    }
#pragma unroll 4
    for (int k = 0; k < K; k++) {
        ulonglong2 va  = *(const ulonglong2*)(s_in + k * LDE + e0);
        ulonglong2 vb  = *(const ulonglong2*)(s_in + k * LDE + e0 + 4);
        ulonglong2 w01 = *(const ulonglong2*)(Wd + k * 256 + 2 * c0);
        ulonglong2 w23 = *(const ulonglong2*)(Wd + k * 256 + 2 * c0 + 4);
        acc[0]  = ffma2(va.x, w01.x, acc[0]);
        acc[1]  = ffma2(va.y, w01.x, acc[1]);
        acc[2]  = ffma2(vb.x, w01.x, acc[2]);
        acc[3]  = ffma2(vb.y, w01.x, acc[3]);
        acc[4]  = ffma2(va.x, w01.y, acc[4]);
        acc[5]  = ffma2(va.y, w01.y, acc[5]);
        acc[6]  = ffma2(vb.x, w01.y, acc[6]);
        acc[7]  = ffma2(vb.y, w01.y, acc[7]);
        acc[8]  = ffma2(va.x, w23.x, acc[8]);
        acc[9]  = ffma2(va.y, w23.x, acc[9]);
        acc[10] = ffma2(vb.x, w23.x, acc[10]);
        acc[11] = ffma2(vb.y, w23.x, acc[11]);
        acc[12] = ffma2(va.x, w23.y, acc[12]);
        acc[13] = ffma2(va.y, w23.y, acc[13]);
        acc[14] = ffma2(vb.x, w23.y, acc[14]);
        acc[15] = ffma2(vb.y, w23.y, acc[15]);
    }
}

// ---------------- scalar FFMA GEMM (node kernels) ----------------
template <int TEc, int K, int LD>
__device__ __forceinline__ void mlp_layer(const float* __restrict__ W,
                                          const float* s_in, float bias,
                                          float* acc, int d) {
#pragma unroll
    for (int e = 0; e < TEc; e++) acc[e] = bias;
#pragma unroll 2
    for (int k = 0; k < K; k += 4) {
        float w0 = W[(k + 0) * D + d];
        float w1 = W[(k + 1) * D + d];
        float w2 = W[(k + 2) * D + d];
        float w3 = W[(k + 3) * D + d];
#pragma unroll
        for (int e = 0; e < TEc; e++) {
            float4 v = *(const float4*)(s_in + e * LD + k);
            acc[e] = fmaf(v.x, w0, acc[e]);
            acc[e] = fmaf(v.y, w1, acc[e]);
            acc[e] = fmaf(v.z, w2, acc[e]);
            acc[e] = fmaf(v.w, w3, acc[e]);
        }
    }
}

// ---------------- node linear: g_hh = h @ W_lin + b ----------------
__global__ void node_lin(const float* __restrict__ h,
                         const float* __restrict__ Wlin,
                         const float* __restrict__ blin) {
    __shared__ __align__(16) float s_in[TN * D];
    int t = threadIdx.x;
    int r0 = blockIdx.x * TN;
    for (int e = 0; e < TN; e++) s_in[e * D + t] = h[(r0 + e) * D + t];
    __syncthreads();
    float acc[TN];
    mlp_layer<TN, 128, 128>(Wlin, s_in, blin[t], acc, t);
#pragma unroll
    for (int e = 0; e < TN; e++) g_hh[(r0 + e) * D + t] = acc[e];
}

// ---------------- edge message + attention (tiled f32x2) ----------------
__global__ void __launch_bounds__(128)
edge_msg(const float* __restrict__ x, const int* __restrict__ ei,
         const float* __restrict__ edge_mask,
         const float* __restrict__ edge_attr,
         const float* __restrict__ be1,
         const float* __restrict__ be2,
         const float* __restrict__ ba1,
         const float* __restrict__ Wa2,
         const float* __restrict__ ba2) {
    extern __shared__ float sm[];
    float* s_att = sm;                      // [260][LDE]  [hr | hc | e3 | 0]
    float* s_msg = s_att + 260 * LDE;       // [132][LDE]  [hc-hr | e3 | 0]
    float* s_m1  = s_msg + 132 * LDE;       // [128][LDE]  A1, then M1
    float* s_w2  = s_m1 + 128 * LDE;        // 128
    float* s_as  = s_w2 + 128;              // TE
    float* s_em  = s_as + TE;               // TE
    float* s_gp  = s_em + TE;               // TE*4
    int*   s_row = (int*)(s_gp + TE * 4);
    int*   s_col = s_row + TE;

    int t = threadIdx.x, lane = t & 31, wid = t >> 5;
    int e0b = blockIdx.x * TE;
    int c0 = (wid << 5) + ((lane & 7) << 2);
    int e0 = (lane >> 3) << 3;

    if (t < TE) {
        s_row[t] = ei[e0b + t];
        s_col[t] = ei[NE + e0b + t];
        s_em[t]  = edge_mask[e0b + t];
    }
    s_w2[t] = Wa2[t];
    __syncthreads();

    // gather (transposed): thread t = feature index
    for (int e = 0; e < TE; e++) {
        float hr = g_hh[s_row[e] * D + t];
        float hc = g_hh[s_col[e] * D + t];
        s_att[t * LDE + e]         = hr;
        s_att[(128 + t) * LDE + e] = hc;
        float v = hc - hr;
        s_msg[t * LDE + e] = v;
        float p = v * v;
#pragma unroll
        for (int o = 16; o > 0; o >>= 1) p += __shfl_down_sync(0xffffffffu, p, o);
        if (lane == 0) s_gp[e * 4 + wid] = p;
    }
    __syncthreads();

    if (t < TE) {
        int e = t;
        float geo = sqrtf(s_gp[e * 4] + s_gp[e * 4 + 1] + s_gp[e * 4 + 2] +
                          s_gp[e * 4 + 3] + 1e-8f);
        int r = s_row[e], c = s_col[e];
        float dx = x[r * 3 + 0] - x[c * 3 + 0];
        float dy = x[r * 3 + 1] - x[c * 3 + 1];
        float dz = x[r * 3 + 2] - x[c * 3 + 2];
        float dist = sqrtf(dx * dx + dy * dy + dz * dz + 1e-8f);
        float ea = edge_attr[e0b + e];
        s_att[256 * LDE + e] = dist;
        s_att[257 * LDE + e] = ea;
        s_att[258 * LDE + e] = geo;
        s_att[259 * LDE + e] = 0.f;
        s_msg[128 * LDE + e] = dist;
        s_msg[129 * LDE + e] = ea;
        s_msg[130 * LDE + e] = geo;
        s_msg[131 * LDE + e] = 0.f;
        g_e3[(e0b + e) * 3 + 0] = dist;
        g_e3[(e0b + e) * 3 + 1] = ea;
        g_e3[(e0b + e) * 3 + 2] = geo;
    }
    __syncthreads();

    u64 acc[16];
    // A1 = silu(att_in @ Wa1 + ba1)
    mlp2t<260>(g_Wa1d, s_att, ba1, acc, c0, e0);
#pragma unroll
    for (int c = 0; c < 4; c++)
#pragma unroll
        for (int p = 0; p < 4; p++)
            silu_store2(&s_m1[(c0 + c) * LDE + e0 + 2 * p], acc[c * 4 + p]);
    __syncthreads();

    // att = sigmoid(A1 @ Wa2 + ba2) * edge_mask
    {
        float b2 = ba2[0];
        for (int i = 0; i < TE / 4; i++) {
            int e = wid * (TE / 4) + i;
            float s = s_m1[lane * LDE + e]        * s_w2[lane] +
                      s_m1[(lane + 32) * LDE + e] * s_w2[lane + 32] +
                      s_m1[(lane + 64) * LDE + e] * s_w2[lane + 64] +
                      s_m1[(lane + 96) * LDE + e] * s_w2[lane + 96];
#pragma unroll
            for (int o = 16; o > 0; o >>= 1) s += __shfl_down_sync(0xffffffffu, s, o);
            if (lane == 0) {
                float z = s + b2;
                s_as[e] = s_em[e] / (1.f + expf(-z));
            }
        }
    }
    __syncthreads();

    // M1 = silu(msg_in @ We1 + be1) -> overwrite s_m1
    mlp2t<132>(g_We1d, s_msg, be1, acc, c0, e0);
    __syncthreads();
#pragma unroll
    for (int c = 0; c < 4; c++)
#pragma unroll
        for (int p = 0; p < 4; p++)
            silu_store2(&s_m1[(c0 + c) * LDE + e0 + 2 * p], acc[c * 4 + p]);
    __syncthreads();

    // msg = (M1 @ We2 + be2) * att ; vector-red scatter
    mlp2t<128>(g_We2d, s_m1, be2, acc, c0, e0);
#pragma unroll
    for (int p = 0; p < 4; p++) {
        int eA = e0 + 2 * p, eB = eA + 1;
        float aA = s_as[eA], aB = s_as[eB];
        float2 v0 = unpk(acc[0 * 4 + p]);
        float2 v1 = unpk(acc[1 * 4 + p]);
        float2 v2 = unpk(acc[2 * 4 + p]);
        float2 v3 = unpk(acc[3 * 4 + p]);
        red4(&g_agg[s_row[eA] * D + c0], v0.x * aA, v1.x * aA, v2.x * aA, v3.x * aA);
        red4(&g_agg[s_row[eB] * D + c0], v0.y * aB, v1.y * aB, v2.y * aB, v3.y * aB);
    }
}

// ---------------- node MLP + residual + LayerNorm + silu -> d_out ----------------
__global__ void node_mlp(const float* __restrict__ Wn1, const float* __restrict__ bn1,
                         const float* __restrict__ Wn2, const float* __restrict__ bn2,
                         const float* __restrict__ ln_g, const float* __restrict__ ln_b,
                         float* __restrict__ out_h) {
    __shared__ __align__(16) float s_a[TN * 128];
    __shared__ __align__(16) float s_t[TN * 128];
    __shared__ float s_mu[TN], s_rs[TN];
    int t = threadIdx.x, lane = t & 31, wid = t >> 5;
    int r0 = blockIdx.x * TN;

    for (int e = 0; e < TN; e++) s_a[e * 128 + t] = g_agg[(r0 + e) * D + t];
    __syncthreads();

    float acc[TN];
    mlp_layer<TN, 128, 128>(Wn1, s_a, bn1[t], acc, t);
#pragma unroll
    for (int e = 0; e < TN; e++) s_t[e * 128 + t] = siluf(acc[e]);
    __syncthreads();

    mlp_layer<TN, 128, 128>(Wn2, s_t, bn2[t], acc, t);
#pragma unroll
    for (int e = 0; e < TN; e++) {
        float v = g_hh[(r0 + e) * D + t] + acc[e];
        s_a[e * 128 + t] = v;
    }
    __syncthreads();

    for (int i = 0; i < TN / 4; i++) {
        int e = wid * (TN / 4) + i;
        float v0 = s_a[e * 128 + lane];
        float v1 = s_a[e * 128 + lane + 32];
        float v2 = s_a[e * 128 + lane + 64];
        float v3 = s_a[e * 128 + lane + 96];
        float s = v0 + v1 + v2 + v3;
        float q = v0 * v0 + v1 * v1 + v2 * v2 + v3 * v3;
#pragma unroll
        for (int o = 16; o > 0; o >>= 1) {
            s += __shfl_down_sync(0xffffffffu, s, o);
            q += __shfl_down_sync(0xffffffffu, q, o);
        }
        if (lane == 0) {
            float mu = s * (1.f / 128.f);
            float var = q * (1.f / 128.f) - mu * mu;
            s_mu[e] = mu;
            s_rs[e] = rsqrtf(var + 1e-5f);
        }
    }
    __syncthreads();

    float g = ln_g[t], bb = ln_b[t];
    for (int e = 0; e < TN; e++) {
        float v = (s_a[e * 128 + t] - s_mu[e]) * s_rs[e] * g + bb;
        out_h[(r0 + e) * D + t] = siluf(v);
    }
}

// ---------------- coord MLP + scatter (tiled f32x2) ----------------
__global__ void __launch_bounds__(128)
edge_coord(const float* __restrict__ x, const int* __restrict__ ei,
           const float* __restrict__ edge_mask,
           const float* __restrict__ hh2,  // = d_out[0:N*D]
           const float* __restrict__ bc1,
           const float* __restrict__ bc2,
           const float* __restrict__ Wc3) {
    extern __shared__ float sm[];
    float* s_in = sm;                      // [260][LDE]; rows 0..127 reused for m2
    float* s_m1 = s_in + 260 * LDE;        // [128][LDE]
    float* s_w3 = s_m1 + 128 * LDE;        // 128
    float* s_mm = s_w3 + 128;              // TE
    float* s_em = s_mm + TE;               // TE
    int*   s_row = (int*)(s_em + TE);
    int*   s_col = s_row + TE;

    int t = threadIdx.x, lane = t & 31, wid = t >> 5;
    int e0b = blockIdx.x * TE;
    int c0 = (wid << 5) + ((lane & 7) << 2);
    int e0 = (lane >> 3) << 3;

    if (t < TE) {
        s_row[t] = ei[e0b + t];
        s_col[t] = ei[NE + e0b + t];
        s_em[t]  = edge_mask[e0b + t];
    }
    s_w3[t] = Wc3[t];
    __syncthreads();

    for (int e = 0; e < TE; e++) {
        s_in[t * LDE + e]         = hh2[s_row[e] * D + t];
        s_in[(128 + t) * LDE + e] = hh2[s_col[e] * D + t];
    }
    if (t < TE) {
        int e = t;
        s_in[256 * LDE + e] = g_e3[(e0b + e) * 3 + 0];
        s_in[257 * LDE + e] = g_e3[(e0b + e) * 3 + 1];
        s_in[258 * LDE + e] = g_e3[(e0b + e) * 3 + 2];
        s_in[259 * LDE + e] = 0.f;
    }
    __syncthreads();

    u64 acc[16];
    mlp2t<260>(g_Wc1d, s_in, bc1, acc, c0, e0);
#pragma unroll
    for (int c = 0; c < 4; c++)
#pragma unroll
        for (int p = 0; p < 4; p++)
            silu_store2(&s_m1[(c0 + c) * LDE + e0 + 2 * p], acc[c * 4 + p]);
    __syncthreads();

    mlp2t<128>(g_Wc2d, s_m1, bc2, acc, c0, e0);
#pragma unroll
    for (int c = 0; c < 4; c++)
#pragma unroll
        for (int p = 0; p < 4; p++)
            silu_store2(&s_in[(c0 + c) * LDE + e0 + 2 * p], acc[c * 4 + p]);  // m2
    __syncthreads();

    // m = m2 @ Wc3 (no bias)
    for (int i = 0; i < TE / 4; i++) {
        int e = wid * (TE / 4) + i;
        float s = s_in[lane * LDE + e]        * s_w3[lane] +
                  s_in[(lane + 32) * LDE + e] * s_w3[lane + 32] +
                  s_in[(lane + 64) * LDE + e] * s_w3[lane + 64] +
                  s_in[(lane + 96) * LDE + e] * s_w3[lane + 96];
#pragma unroll
        for (int o = 16; o > 0; o >>= 1) s += __shfl_down_sync(0xffffffffu, s, o);
        if (lane == 0) s_mm[e] = s * s_em[e];
    }
    __syncthreads();

    if (t < TE) {
        int e = t;
        int r = s_row[e], c = s_col[e];
        float dx = x[r * 3 + 0] - x[c * 3 + 0];
        float dy = x[r * 3 + 1] - x[c * 3 + 1];
        float dz = x[r * 3 + 2] - x[c * 3 + 2];
        float dist = s_in[256 * LDE + e];
        float inv = 1.f / (dist + 1.f);
        float m = s_mm[e];
        atomicAdd(&g_aggx[r * 3 + 0], dx * inv * m);
        atomicAdd(&g_aggx[r * 3 + 1], dy * inv * m);
        atomicAdd(&g_aggx[r * 3 + 2], dz * inv * m);
    }
}

__global__ void finalize_x(const float* __restrict__ x,
                           const float* __restrict__ node_mask,
                           float* __restrict__ out) {
    int i = blockIdx.x * blockDim.x + threadIdx.x;
    if (i < NN * 3) {
        out[i] = (x[i] + g_aggx[i] * (1.f / 100.f)) * node_mask[i / 3];
    }
}

// ---------------- launcher ----------------
extern "C" void kernel_launch(void* const* d_in, const int* in_sizes, int n_in,
                              void* d_out, int out_size) {
    const float* h         = (const float*)d_in[0];
    const float* x         = (const float*)d_in[1];
    const int*   ei        = (const int*)d_in[2];
    const float* node_mask = (const float*)d_in[3];
    const float* edge_mask = (const float*)d_in[4];
    const float* edge_attr = (const float*)d_in[5];
    const float* Wlin = (const float*)d_in[6];
    const float* blin = (const float*)d_in[7];
    const float* We1  = (const float*)d_in[8];
    const float* be1  = (const float*)d_in[9];
    const float* We2  = (const float*)d_in[10];
    const float* be2  = (const float*)d_in[11];
    const float* Wn1  = (const float*)d_in[12];
    const float* bn1  = (const float*)d_in[13];
    const float* Wn2  = (const float*)d_in[14];
    const float* bn2  = (const float*)d_in[15];
    const float* Wa1  = (const float*)d_in[16];
    const float* ba1  = (const float*)d_in[17];
    const float* Wa2  = (const float*)d_in[18];
    const float* ba2  = (const float*)d_in[19];
    const float* ln_g = (const float*)d_in[20];
    const float* ln_b = (const float*)d_in[21];
    const float* Wc1  = (const float*)d_in[22];
    const float* bc1  = (const float*)d_in[23];
    const float* Wc2  = (const float*)d_in[24];
    const float* bc2  = (const float*)d_in[25];
    const float* Wc3  = (const float*)d_in[26];
    float* out = (float*)d_out;

    const int SMEM_MSG = (260 * LDE + 132 * LDE + 128 * LDE + 128 + TE + TE + TE * 4) * 4
                         + 2 * TE * 4;
    const int SMEM_CRD = (260 * LDE + 128 * LDE + 128 + TE + TE) * 4 + 2 * TE * 4;

    cudaFuncSetAttribute(edge_msg, cudaFuncAttributeMaxDynamicSharedMemorySize, SMEM_MSG);
    cudaFuncSetAttribute(edge_coord, cudaFuncAttributeMaxDynamicSharedMemorySize, SMEM_CRD);

    prep_weights<<<dim3(64, 5), 256>>>(Wa1, We1, We2, Wc1, Wc2);
    zero_scratch<<<1024, 256>>>();
    node_lin<<<NN / TN, 128>>>(h, Wlin, blin);
    edge_msg<<<NE / TE, 128, SMEM_MSG>>>(x, ei, edge_mask, edge_attr,
                                         be1, be2, ba1, Wa2, ba2);
    node_mlp<<<NN / TN, 128>>>(Wn1, bn1, Wn2, bn2, ln_g, ln_b, out);
    edge_coord<<<NE / TE, 128, SMEM_CRD>>>(x, ei, edge_mask, out, bc1, bc2, Wc3);
    finalize_x<<<(NN * 3 + 255) / 256, 256>>>(x, node_mask, out + NN * D);
}

// round 5
// speedup vs baseline: 4.5144x; 4.5144x over previous
#include <cuda_runtime.h>
#include <math.h>

#define NN 20000
#define NE 640000
#define D  128
#define TE 32
#define TN 32

typedef unsigned int u32;

// ---------------- scratch (static device memory; no allocations) ----------------
__device__ float g_hh[NN * D];
__device__ float g_agg[NN * D];
__device__ float g_aggx[NN * 3];
__device__ float g_e3[NE * 3];
// fragment-permuted tf32 weights: [s][nt][lane][2]
__device__ __align__(16) float g_Wa1p[33 * 16 * 64];
__device__ __align__(16) float g_We1p[17 * 16 * 64];
__device__ __align__(16) float g_We2p[16 * 16 * 64];
__device__ __align__(16) float g_Wc1p[33 * 16 * 64];
__device__ __align__(16) float g_Wc2p[16 * 16 * 64];

__device__ __forceinline__ float siluf(float v) { return v / (1.f + expf(-v)); }

__device__ __forceinline__ u32 tf32r(float v) {
    u32 r;
    asm("cvt.rna.tf32.f32 %0, %1;" : "=r"(r) : "f"(v));
    return r;
}
__device__ __forceinline__ void mma8(float* c, uint4 a, uint2 b) {
    asm volatile(
        "mma.sync.aligned.m16n8k8.row.col.f32.tf32.tf32.f32 "
        "{%0,%1,%2,%3}, {%4,%5,%6,%7}, {%8,%9}, {%0,%1,%2,%3};"
        : "+f"(c[0]), "+f"(c[1]), "+f"(c[2]), "+f"(c[3])
        : "r"(a.x), "r"(a.y), "r"(a.z), "r"(a.w), "r"(b.x), "r"(b.y));
}
__device__ __forceinline__ void red2(float* p, float a, float b) {
    asm volatile("red.global.add.v2.f32 [%0], {%1, %2};"
                 :: "l"(p), "f"(a), "f"(b) : "memory");
}

// store value (edge e, feature k) into fragment-permuted A layout (tf32-rounded)
__device__ __forceinline__ void stp(float* b0, float* b1, int e, int k, float v) {
    float* base = (e & 16) ? b1 : b0;
    int addr = (((k >> 3) * 32 + (((e & 7) << 2) | (k & 3))) << 2) +
               (((e & 8) >> 3) | ((k & 4) >> 1));
    ((u32*)base)[addr] = tf32r(v);
}

// ---------------- weight permute+tf32 prep ----------------
__global__ void prep_weights(const float* __restrict__ Wa1, const float* __restrict__ We1,
                             const float* __restrict__ We2, const float* __restrict__ Wc1,
                             const float* __restrict__ Wc2) {
    int m = blockIdx.y;
    const float* src; float* dst; int K, NS;
    if (m == 0)      { src = Wa1; dst = g_Wa1p; K = 259; NS = 33; }
    else if (m == 1) { src = We1; dst = g_We1p; K = 131; NS = 17; }
    else if (m == 2) { src = We2; dst = g_We2p; K = 128; NS = 16; }
    else if (m == 3) { src = Wc1; dst = g_Wc1p; K = 259; NS = 33; }
    else             { src = Wc2; dst = g_Wc2p; K = 128; NS = 16; }
    int idx = blockIdx.x * blockDim.x + threadIdx.x;
    if (idx >= NS * 16 * 32) return;
    int l = idx & 31, nt = (idx >> 5) & 15, s = idx >> 9;
    int k0 = s * 8 + (l & 3);
    int cc = nt * 8 + (l >> 2);
    float b0 = (k0 < K) ? src[k0 * 128 + cc] : 0.f;
    float b1 = (k0 + 4 < K) ? src[(k0 + 4) * 128 + cc] : 0.f;
    u32* d = (u32*)(dst + (s * 16 + nt) * 64 + l * 2);
    d[0] = tf32r(b0);
    d[1] = tf32r(b1);
}

__global__ void zero_scratch() {
    int idx = blockIdx.x * blockDim.x + threadIdx.x;
    int stride = gridDim.x * blockDim.x;
    for (int i = idx; i < NN * D; i += stride) g_agg[i] = 0.f;
    for (int i = idx; i < NN * 3; i += stride) g_aggx[i] = 0.f;
}

// ---------------- tf32 GEMM mainloop: C[32e x 128c], warp w owns cols w*32..+31 ----
template <int NS>
__device__ __forceinline__ void gemm2(const float* sA0, const float* sA1,
                                      const float* __restrict__ gW,
                                      int lane, int w, float (*c)[4]) {
#pragma unroll 2
    for (int s = 0; s < NS; s++) {
        uint4 a0 = ((const uint4*)sA0)[s * 32 + lane];
        uint4 a1 = ((const uint4*)sA1)[s * 32 + lane];
        uint2 b[4];
#pragma unroll
        for (int j = 0; j < 4; j++)
            b[j] = *(const uint2*)(gW + (s * 16 + w * 4 + j) * 64 + lane * 2);
#pragma unroll
        for (int j = 0; j < 4; j++) {
            mma8(c[j], a0, b[j]);
            mma8(c[4 + j], a1, b[j]);
        }
    }
}
__device__ __forceinline__ void init_bias(const float* __restrict__ bias,
                                          int lane, int w, float (*c)[4]) {
#pragma unroll
    for (int j = 0; j < 4; j++) {
        float2 bb = *(const float2*)(bias + w * 32 + j * 8 + (lane & 3) * 2);
        c[j][0] = bb.x; c[j][1] = bb.y; c[j][2] = bb.x; c[j][3] = bb.y;
        c[4 + j][0] = bb.x; c[4 + j][1] = bb.y; c[4 + j][2] = bb.x; c[4 + j][3] = bb.y;
    }
}

// ---------------- scalar FFMA GEMM (node kernels) ----------------
template <int TEc, int K, int LD>
__device__ __forceinline__ void mlp_layer(const float* __restrict__ W,
                                          const float* s_in, float bias,
                                          float* acc, int d) {
#pragma unroll
    for (int e = 0; e < TEc; e++) acc[e] = bias;
#pragma unroll 2
    for (int k = 0; k < K; k += 4) {
        float w0 = W[(k + 0) * D + d];
        float w1 = W[(k + 1) * D + d];
        float w2 = W[(k + 2) * D + d];
        float w3 = W[(k + 3) * D + d];
#pragma unroll
        for (int e = 0; e < TEc; e++) {
            float4 v = *(const float4*)(s_in + e * LD + k);
            acc[e] = fmaf(v.x, w0, acc[e]);
            acc[e] = fmaf(v.y, w1, acc[e]);
            acc[e] = fmaf(v.z, w2, acc[e]);
            acc[e] = fmaf(v.w, w3, acc[e]);
        }
    }
}

// ---------------- node linear ----------------
__global__ void node_lin(const float* __restrict__ h,
                         const float* __restrict__ Wlin,
                         const float* __restrict__ blin) {
    __shared__ __align__(16) float s_in[TN * D];
    int t = threadIdx.x;
    int r0 = blockIdx.x * TN;
    for (int e = 0; e < TN; e++) s_in[e * D + t] = h[(r0 + e) * D + t];
    __syncthreads();
    float acc[TN];
    mlp_layer<TN, 128, 128>(Wlin, s_in, blin[t], acc, t);
#pragma unroll
    for (int e = 0; e < TN; e++) g_hh[(r0 + e) * D + t] = acc[e];
}

// ---------------- edge message + attention (tf32 mma) ----------------
__global__ void __launch_bounds__(128, 4)
edge_msg(const float* __restrict__ x, const int* __restrict__ ei,
         const float* __restrict__ edge_mask,
         const float* __restrict__ edge_attr,
         const float* __restrict__ be1, const float* __restrict__ be2,
         const float* __restrict__ ba1,
         const float* __restrict__ Wa2, const float* __restrict__ ba2) {
    extern __shared__ float sm[];
    float* sA0  = sm;                 // 4224: att-in frag region m0 (33 ksteps); reused for M1-perm
    float* sA1  = sA0 + 4224;         // 4224: att-in m1
    float* sM0  = sA1 + 4224;         // 2176: msg-in m0 (17 ksteps)
    float* sM1  = sM0 + 2176;         // 2176: msg-in m1
    float* s_gp = sM1 + 2176;         // 128: geo partials, then gate partials
    float* s_at = s_gp + 128;         // 32: att per edge
    float* s_em = s_at + 32;          // 32
    int*   s_row = (int*)(s_em + 32); // 32
    int*   s_col = s_row + 32;        // 32

    int t = threadIdx.x, lane = t & 31, w = t >> 5;
    int e0b = blockIdx.x * TE;

    if (t < TE) {
        s_row[t] = ei[e0b + t];
        s_col[t] = ei[NE + e0b + t];
        s_em[t]  = edge_mask[e0b + t];
    }
    __syncthreads();

    // gather: thread t = feature index 0..127
    {
        float p = 0.f;
        for (int e = 0; e < TE; e++) {
            float hr = g_hh[s_row[e] * D + t];
            float hc = g_hh[s_col[e] * D + t];
            stp(sA0, sA1, e, t, hr);
            stp(sA0, sA1, e, 128 + t, hc);
            float v = hc - hr;
            stp(sM0, sM1, e, t, v);
            float q = v * v;
#pragma unroll
            for (int o = 16; o > 0; o >>= 1) q += __shfl_down_sync(0xffffffffu, q, o);
            if (lane == 0) s_gp[e * 4 + w] = q;
            (void)p;
        }
    }
    __syncthreads();

    if (t < TE) {
        int e = t;
        float geo = sqrtf(s_gp[e * 4] + s_gp[e * 4 + 1] + s_gp[e * 4 + 2] +
                          s_gp[e * 4 + 3] + 1e-8f);
        int r = s_row[e], c = s_col[e];
        float dx = x[r * 3 + 0] - x[c * 3 + 0];
        float dy = x[r * 3 + 1] - x[c * 3 + 1];
        float dz = x[r * 3 + 2] - x[c * 3 + 2];
        float dist = sqrtf(dx * dx + dy * dy + dz * dz + 1e-8f);
        float ea = edge_attr[e0b + e];
        // att-in features 256..263 (pad), msg-in 128..135 (pad)
        stp(sA0, sA1, e, 256, dist); stp(sA0, sA1, e, 257, ea);
        stp(sA0, sA1, e, 258, geo);
#pragma unroll
        for (int k = 259; k < 264; k++) stp(sA0, sA1, e, k, 0.f);
        stp(sM0, sM1, e, 128, dist); stp(sM0, sM1, e, 129, ea);
        stp(sM0, sM1, e, 130, geo);
#pragma unroll
        for (int k = 131; k < 136; k++) stp(sM0, sM1, e, k, 0.f);
        g_e3[(e0b + e) * 3 + 0] = dist;
        g_e3[(e0b + e) * 3 + 1] = ea;
        g_e3[(e0b + e) * 3 + 2] = geo;
    }
    __syncthreads();

    // layer A1: [32,264] @ Wa1 -> gate partials
    float cA[8][4];
    init_bias(ba1, lane, w, cA);
    gemm2<33>(sA0, sA1, g_Wa1p, lane, w, cA);
    {
        float p0 = 0.f, p1 = 0.f, p2 = 0.f, p3 = 0.f;
#pragma unroll
        for (int j = 0; j < 4; j++) {
            float2 w2 = *(const float2*)(Wa2 + w * 32 + j * 8 + (lane & 3) * 2);
            p0 += siluf(cA[j][0]) * w2.x + siluf(cA[j][1]) * w2.y;
            p1 += siluf(cA[j][2]) * w2.x + siluf(cA[j][3]) * w2.y;
            p2 += siluf(cA[4 + j][0]) * w2.x + siluf(cA[4 + j][1]) * w2.y;
            p3 += siluf(cA[4 + j][2]) * w2.x + siluf(cA[4 + j][3]) * w2.y;
        }
        p0 += __shfl_down_sync(0xffffffffu, p0, 2, 4); p0 += __shfl_down_sync(0xffffffffu, p0, 1, 4);
        p1 += __shfl_down_sync(0xffffffffu, p1, 2, 4); p1 += __shfl_down_sync(0xffffffffu, p1, 1, 4);
        p2 += __shfl_down_sync(0xffffffffu, p2, 2, 4); p2 += __shfl_down_sync(0xffffffffu, p2, 1, 4);
        p3 += __shfl_down_sync(0xffffffffu, p3, 2, 4); p3 += __shfl_down_sync(0xffffffffu, p3, 1, 4);
        if ((lane & 3) == 0) {
            int g = lane >> 2;
            s_gp[g * 4 + w]        = p0;
            s_gp[(g + 8) * 4 + w]  = p1;
            s_gp[(g + 16) * 4 + w] = p2;
            s_gp[(g + 24) * 4 + w] = p3;
        }
    }

    // layer M1: [32,136] @ We1 (reads sM*, independent of sA*)
    float cM[8][4];
    init_bias(be1, lane, w, cM);
    gemm2<17>(sM0, sM1, g_We1p, lane, w, cM);
    __syncthreads();  // all warps done reading sA* and writing s_gp

    // write silu(M1) fragment-permuted into sA* (alias); finalize att gate
#pragma unroll
    for (int j = 0; j < 4; j++) {
        int n = w * 32 + j * 8 + (lane & 3) * 2;
        int g = lane >> 2;
#pragma unroll
        for (int m = 0; m < 2; m++) {
            int e = g + m * 16;
            stp(sA0, sA1, e, n, siluf(cM[m * 4 + j][0]));
            stp(sA0, sA1, e, n + 1, siluf(cM[m * 4 + j][1]));
            stp(sA0, sA1, e + 8, n, siluf(cM[m * 4 + j][2]));
            stp(sA0, sA1, e + 8, n + 1, siluf(cM[m * 4 + j][3]));
        }
    }
    if (t < TE) {
        float z = s_gp[t * 4] + s_gp[t * 4 + 1] + s_gp[t * 4 + 2] + s_gp[t * 4 + 3] + ba2[0];
        s_at[t] = s_em[t] / (1.f + expf(-z));
    }
    __syncthreads();

    // layer MSG: [32,128] @ We2 ; scale by att ; scatter
    float cO[8][4];
    init_bias(be2, lane, w, cO);
    gemm2<16>(sA0, sA1, g_We2p, lane, w, cO);
#pragma unroll
    for (int j = 0; j < 4; j++) {
        int n = w * 32 + j * 8 + (lane & 3) * 2;
        int g = lane >> 2;
#pragma unroll
        for (int m = 0; m < 2; m++) {
            int e = g + m * 16;
            float aL = s_at[e], aH = s_at[e + 8];
            red2(&g_agg[s_row[e] * D + n], cO[m * 4 + j][0] * aL, cO[m * 4 + j][1] * aL);
            red2(&g_agg[s_row[e + 8] * D + n], cO[m * 4 + j][2] * aH, cO[m * 4 + j][3] * aH);
        }
    }
}

// ---------------- node MLP + residual + LN + silu -> d_out ----------------
__global__ void node_mlp(const float* __restrict__ Wn1, const float* __restrict__ bn1,
                         const float* __restrict__ Wn2, const float* __restrict__ bn2,
                         const float* __restrict__ ln_g, const float* __restrict__ ln_b,
                         float* __restrict__ out_h) {
    __shared__ __align__(16) float s_a[TN * 128];
    __shared__ __align__(16) float s_t[TN * 128];
    __shared__ float s_mu[TN], s_rs[TN];
    int t = threadIdx.x, lane = t & 31, wid = t >> 5;
    int r0 = blockIdx.x * TN;

    for (int e = 0; e < TN; e++) s_a[e * 128 + t] = g_agg[(r0 + e) * D + t];
    __syncthreads();

    float acc[TN];
    mlp_layer<TN, 128, 128>(Wn1, s_a, bn1[t], acc, t);
#pragma unroll
    for (int e = 0; e < TN; e++) s_t[e * 128 + t] = siluf(acc[e]);
    __syncthreads();

    mlp_layer<TN, 128, 128>(Wn2, s_t, bn2[t], acc, t);
#pragma unroll
    for (int e = 0; e < TN; e++) {
        float v = g_hh[(r0 + e) * D + t] + acc[e];
        s_a[e * 128 + t] = v;
    }
    __syncthreads();

    for (int i = 0; i < TN / 4; i++) {
        int e = wid * (TN / 4) + i;
        float v0 = s_a[e * 128 + lane];
        float v1 = s_a[e * 128 + lane + 32];
        float v2 = s_a[e * 128 + lane + 64];
        float v3 = s_a[e * 128 + lane + 96];
        float s = v0 + v1 + v2 + v3;
        float q = v0 * v0 + v1 * v1 + v2 * v2 + v3 * v3;
#pragma unroll
        for (int o = 16; o > 0; o >>= 1) {
            s += __shfl_down_sync(0xffffffffu, s, o);
            q += __shfl_down_sync(0xffffffffu, q, o);
        }
        if (lane == 0) {
            float mu = s * (1.f / 128.f);
            float var = q * (1.f / 128.f) - mu * mu;
            s_mu[e] = mu;
            s_rs[e] = rsqrtf(var + 1e-5f);
        }
    }
    __syncthreads();

    float g = ln_g[t], bb = ln_b[t];
    for (int e = 0; e < TN; e++) {
        float v = (s_a[e * 128 + t] - s_mu[e]) * s_rs[e] * g + bb;
        out_h[(r0 + e) * D + t] = siluf(v);
    }
}

// ---------------- coord MLP + scatter (tf32 mma) ----------------
__global__ void __launch_bounds__(128, 4)
edge_coord(const float* __restrict__ x, const int* __restrict__ ei,
           const float* __restrict__ edge_mask,
           const float* __restrict__ hh2,
           const float* __restrict__ bc1, const float* __restrict__ bc2,
           const float* __restrict__ Wc3) {
    extern __shared__ float sm[];
    float* sA0  = sm;                 // 4224 (33 ksteps); reused for M1-perm
    float* sA1  = sA0 + 4224;         // 4224
    float* s_gp = sA1 + 4224;         // 128
    float* s_mm = s_gp + 128;         // 32
    float* s_em = s_mm + 32;          // 32
    float* s_d  = s_em + 32;          // 32 dist
    int*   s_row = (int*)(s_d + 32);
    int*   s_col = s_row + 32;

    int t = threadIdx.x, lane = t & 31, w = t >> 5;
    int e0b = blockIdx.x * TE;

    if (t < TE) {
        s_row[t] = ei[e0b + t];
        s_col[t] = ei[NE + e0b + t];
        s_em[t]  = edge_mask[e0b + t];
    }
    __syncthreads();

    for (int e = 0; e < TE; e++) {
        float hr = hh2[s_row[e] * D + t];
        float hc = hh2[s_col[e] * D + t];
        stp(sA0, sA1, e, t, hr);
        stp(sA0, sA1, e, 128 + t, hc);
    }
    if (t < TE) {
        int e = t;
        float dist = g_e3[(e0b + e) * 3 + 0];
        float ea   = g_e3[(e0b + e) * 3 + 1];
        float geo  = g_e3[(e0b + e) * 3 + 2];
        stp(sA0, sA1, e, 256, dist); stp(sA0, sA1, e, 257, ea);
        stp(sA0, sA1, e, 258, geo);
#pragma unroll
        for (int k = 259; k < 264; k++) stp(sA0, sA1, e, k, 0.f);
        s_d[e] = dist;
    }
    __syncthreads();

    float c1[8][4];
    init_bias(bc1, lane, w, c1);
    gemm2<33>(sA0, sA1, g_Wc1p, lane, w, c1);
    __syncthreads();  // everyone done reading sA*

#pragma unroll
    for (int j = 0; j < 4; j++) {
        int n = w * 32 + j * 8 + (lane & 3) * 2;
        int g = lane >> 2;
#pragma unroll
        for (int m = 0; m < 2; m++) {
            int e = g + m * 16;
            stp(sA0, sA1, e, n, siluf(c1[m * 4 + j][0]));
            stp(sA0, sA1, e, n + 1, siluf(c1[m * 4 + j][1]));
            stp(sA0, sA1, e + 8, n, siluf(c1[m * 4 + j][2]));
            stp(sA0, sA1, e + 8, n + 1, siluf(c1[m * 4 + j][3]));
        }
    }
    __syncthreads();

    float c2[8][4];
    init_bias(bc2, lane, w, c2);
    gemm2<16>(sA0, sA1, g_Wc2p, lane, w, c2);

    // m = silu(M2) @ Wc3 via fragment reduction
    {
        float p0 = 0.f, p1 = 0.f, p2 = 0.f, p3 = 0.f;
#pragma unroll
        for (int j = 0; j < 4; j++) {
            float2 w3 = *(const float2*)(Wc3 + w * 32 + j * 8 + (lane & 3) * 2);
            p0 += siluf(c2[j][0]) * w3.x + siluf(c2[j][1]) * w3.y;
            p1 += siluf(c2[j][2]) * w3.x + siluf(c2[j][3]) * w3.y;
            p2 += siluf(c2[4 + j][0]) * w3.x + siluf(c2[4 + j][1]) * w3.y;
            p3 += siluf(c2[4 + j][2]) * w3.x + siluf(c2[4 + j][3]) * w3.y;
        }
        p0 += __shfl_down_sync(0xffffffffu, p0, 2, 4); p0 += __shfl_down_sync(0xffffffffu, p0, 1, 4);
        p1 += __shfl_down_sync(0xffffffffu, p1, 2, 4); p1 += __shfl_down_sync(0xffffffffu, p1, 1, 4);
        p2 += __shfl_down_sync(0xffffffffu, p2, 2, 4); p2 += __shfl_down_sync(0xffffffffu, p2, 1, 4);
        p3 += __shfl_down_sync(0xffffffffu, p3, 2, 4); p3 += __shfl_down_sync(0xffffffffu, p3, 1, 4);
        if ((lane & 3) == 0) {
            int g = lane >> 2;
            s_gp[g * 4 + w]        = p0;
            s_gp[(g + 8) * 4 + w]  = p1;
            s_gp[(g + 16) * 4 + w] = p2;
            s_gp[(g + 24) * 4 + w] = p3;
        }
    }
    __syncthreads();

    if (t < TE) {
        int e = t;
        float mval = (s_gp[e * 4] + s_gp[e * 4 + 1] + s_gp[e * 4 + 2] + s_gp[e * 4 + 3])
                     * s_em[e];
        int r = s_row[e], c = s_col[e];
        float dx = x[r * 3 + 0] - x[c * 3 + 0];
        float dy = x[r * 3 + 1] - x[c * 3 + 1];
        float dz = x[r * 3 + 2] - x[c * 3 + 2];
        float inv = 1.f / (s_d[e] + 1.f);
        atomicAdd(&g_aggx[r * 3 + 0], dx * inv * mval);
        atomicAdd(&g_aggx[r * 3 + 1], dy * inv * mval);
        atomicAdd(&g_aggx[r * 3 + 2], dz * inv * mval);
    }
}

__global__ void finalize_x(const float* __restrict__ x,
                           const float* __restrict__ node_mask,
                           float* __restrict__ out) {
    int i = blockIdx.x * blockDim.x + threadIdx.x;
    if (i < NN * 3) {
        out[i] = (x[i] + g_aggx[i] * (1.f / 100.f)) * node_mask[i / 3];
    }
}

// ---------------- launcher ----------------
extern "C" void kernel_launch(void* const* d_in, const int* in_sizes, int n_in,
                              void* d_out, int out_size) {
    const float* h         = (const float*)d_in[0];
    const float* x         = (const float*)d_in[1];
    const int*   ei        = (const int*)d_in[2];
    const float* node_mask = (const float*)d_in[3];
    const float* edge_mask = (const float*)d_in[4];
    const float* edge_attr = (const float*)d_in[5];
    const float* Wlin = (const float*)d_in[6];
    const float* blin = (const float*)d_in[7];
    const float* We1  = (const float*)d_in[8];
    const float* be1  = (const float*)d_in[9];
    const float* We2  = (const float*)d_in[10];
    const float* be2  = (const float*)d_in[11];
    const float* Wn1  = (const float*)d_in[12];
    const float* bn1  = (const float*)d_in[13];
    const float* Wn2  = (const float*)d_in[14];
    const float* bn2  = (const float*)d_in[15];
    const float* Wa1  = (const float*)d_in[16];
    const float* ba1  = (const float*)d_in[17];
    const float* Wa2  = (const float*)d_in[18];
    const float* ba2  = (const float*)d_in[19];
    const float* ln_g = (const float*)d_in[20];
    const float* ln_b = (const float*)d_in[21];
    const float* Wc1  = (const float*)d_in[22];
    const float* bc1  = (const float*)d_in[23];
    const float* Wc2  = (const float*)d_in[24];
    const float* bc2  = (const float*)d_in[25];
    const float* Wc3  = (const float*)d_in[26];
    float* out = (float*)d_out;

    const int SMEM_MSG = (4224 + 4224 + 2176 + 2176 + 128 + 32 + 32) * 4 + 2 * 32 * 4;
    const int SMEM_CRD = (4224 + 4224 + 128 + 32 + 32 + 32) * 4 + 2 * 32 * 4;

    cudaFuncSetAttribute(edge_msg, cudaFuncAttributeMaxDynamicSharedMemorySize, SMEM_MSG);
    cudaFuncSetAttribute(edge_coord, cudaFuncAttributeMaxDynamicSharedMemorySize, SMEM_CRD);

    prep_weights<<<dim3(66, 5), 256>>>(Wa1, We1, We2, Wc1, Wc2);
    zero_scratch<<<1024, 256>>>();
    node_lin<<<NN / TN, 128>>>(h, Wlin, blin);
    edge_msg<<<NE / TE, 128, SMEM_MSG>>>(x, ei, edge_mask, edge_attr,
                                         be1, be2, ba1, Wa2, ba2);
    node_mlp<<<NN / TN, 128>>>(Wn1, bn1, Wn2, bn2, ln_g, ln_b, out);
    edge_coord<<<NE / TE, 128, SMEM_CRD>>>(x, ei, edge_mask, out, bc1, bc2, Wc3);
    finalize_x<<<(NN * 3 + 255) / 256, 256>>>(x, node_mask, out + NN * D);
}

// round 6
// speedup vs baseline: 5.5537x; 1.2302x over previous
#include <cuda_runtime.h>
#include <math.h>

#define NN 20000
#define NE 640000
#define D  128
#define TE 32
#define TN 32

typedef unsigned int u32;

// ---------------- scratch (static device memory; no allocations) ----------------
__device__ float g_hh[NN * D];
__device__ float g_agg[NN * D];
__device__ float g_aggx[NN * 3];
__device__ float g_e3[NE * 3];
// fragment-permuted tf32 weights: [s][nt][lane][2]
__device__ __align__(16) float g_Wa1p[33 * 16 * 64];
__device__ __align__(16) float g_We1p[33 * 16 * 64];  // fused [-We1|+We1|We1_e3]
__device__ __align__(16) float g_We2p[16 * 16 * 64];
__device__ __align__(16) float g_Wc1p[33 * 16 * 64];
__device__ __align__(16) float g_Wc2p[16 * 16 * 64];

__device__ __forceinline__ float siluf(float v) { return v / (1.f + expf(-v)); }

__device__ __forceinline__ u32 tf32r(float v) {
    u32 r;
    asm("cvt.rna.tf32.f32 %0, %1;" : "=r"(r) : "f"(v));
    return r;
}
__device__ __forceinline__ void mma8(float* c, uint4 a, uint2 b) {
    asm volatile(
        "mma.sync.aligned.m16n8k8.row.col.f32.tf32.tf32.f32 "
        "{%0,%1,%2,%3}, {%4,%5,%6,%7}, {%8,%9}, {%0,%1,%2,%3};"
        : "+f"(c[0]), "+f"(c[1]), "+f"(c[2]), "+f"(c[3])
        : "r"(a.x), "r"(a.y), "r"(a.z), "r"(a.w), "r"(b.x), "r"(b.y));
}
__device__ __forceinline__ void red2(float* p, float a, float b) {
    asm volatile("red.global.add.v2.f32 [%0], {%1, %2};"
                 :: "l"(p), "f"(a), "f"(b) : "memory");
}

// store value (edge e, feature k) into fragment-permuted A layout (tf32-rounded)
__device__ __forceinline__ void stp(float* b0, float* b1, int e, int k, float v) {
    float* base = (e & 16) ? b1 : b0;
    int addr = (((k >> 3) * 32 + (((e & 7) << 2) | (k & 3))) << 2) +
               (((e & 8) >> 3) | ((k & 4) >> 1));
    ((u32*)base)[addr] = tf32r(v);
}

// ---------------- weight permute+tf32 prep ----------------
__global__ void prep_weights(const float* __restrict__ Wa1, const float* __restrict__ We1,
                             const float* __restrict__ We2, const float* __restrict__ Wc1,
                             const float* __restrict__ Wc2) {
    int m = blockIdx.y;
    const float* src; float* dst; int K, NS;
    if (m == 0)      { src = Wa1; dst = g_Wa1p; K = 259; NS = 33; }
    else if (m == 1) { src = We1; dst = g_We1p; K = 264; NS = 33; }
    else if (m == 2) { src = We2; dst = g_We2p; K = 128; NS = 16; }
    else if (m == 3) { src = Wc1; dst = g_Wc1p; K = 259; NS = 33; }
    else             { src = Wc2; dst = g_Wc2p; K = 128; NS = 16; }
    int idx = blockIdx.x * blockDim.x + threadIdx.x;
    if (idx >= NS * 16 * 32) return;
    int l = idx & 31, nt = (idx >> 5) & 15, s = idx >> 9;
    int k0 = s * 8 + (l & 3);
    int cc = nt * 8 + (l >> 2);
    float b0, b1;
    if (m == 1) {
        // fused We1': rows 0..127 = -We1[k], 128..258 = +We1[k-128], rest 0
        auto val = [&](int k) -> float {
            if (k < 128) return -src[k * 128 + cc];
            if (k < 259) return src[(k - 128) * 128 + cc];
            return 0.f;
        };
        b0 = val(k0);
        b1 = val(k0 + 4);
    } else {
        b0 = (k0 < K) ? src[k0 * 128 + cc] : 0.f;
        b1 = (k0 + 4 < K) ? src[(k0 + 4) * 128 + cc] : 0.f;
    }
    u32* d = (u32*)(dst + (s * 16 + nt) * 64 + l * 2);
    d[0] = tf32r(b0);
    d[1] = tf32r(b1);
}

__global__ void zero_scratch() {
    int idx = blockIdx.x * blockDim.x + threadIdx.x;
    int stride = gridDim.x * blockDim.x;
    for (int i = idx; i < NN * D; i += stride) g_agg[i] = 0.f;
    for (int i = idx; i < NN * 3; i += stride) g_aggx[i] = 0.f;
}

// ---------------- tf32 GEMM mainloop ----------------
template <int NS>
__device__ __forceinline__ void gemm2(const float* sA0, const float* sA1,
                                      const float* __restrict__ gW,
                                      int lane, int w, float (*c)[4]) {
#pragma unroll 2
    for (int s = 0; s < NS; s++) {
        uint4 a0 = ((const uint4*)sA0)[s * 32 + lane];
        uint4 a1 = ((const uint4*)sA1)[s * 32 + lane];
        uint2 b[4];
#pragma unroll
        for (int j = 0; j < 4; j++)
            b[j] = *(const uint2*)(gW + (s * 16 + w * 4 + j) * 64 + lane * 2);
#pragma unroll
        for (int j = 0; j < 4; j++) {
            mma8(c[j], a0, b[j]);
            mma8(c[4 + j], a1, b[j]);
        }
    }
}
__device__ __forceinline__ void init_bias(const float* __restrict__ bias,
                                          int lane, int w, float (*c)[4]) {
#pragma unroll
    for (int j = 0; j < 4; j++) {
        float2 bb = *(const float2*)(bias + w * 32 + j * 8 + (lane & 3) * 2);
        c[j][0] = bb.x; c[j][1] = bb.y; c[j][2] = bb.x; c[j][3] = bb.y;
        c[4 + j][0] = bb.x; c[4 + j][1] = bb.y; c[4 + j][2] = bb.x; c[4 + j][3] = bb.y;
    }
}

// ---------------- scalar FFMA GEMM (node kernels) ----------------
template <int TEc, int K, int LD>
__device__ __forceinline__ void mlp_layer(const float* __restrict__ W,
                                          const float* s_in, float bias,
                                          float* acc, int d) {
#pragma unroll
    for (int e = 0; e < TEc; e++) acc[e] = bias;
#pragma unroll 2
    for (int k = 0; k < K; k += 4) {
        float w0 = W[(k + 0) * D + d];
        float w1 = W[(k + 1) * D + d];
        float w2 = W[(k + 2) * D + d];
        float w3 = W[(k + 3) * D + d];
#pragma unroll
        for (int e = 0; e < TEc; e++) {
            float4 v = *(const float4*)(s_in + e * LD + k);
            acc[e] = fmaf(v.x, w0, acc[e]);
            acc[e] = fmaf(v.y, w1, acc[e]);
            acc[e] = fmaf(v.z, w2, acc[e]);
            acc[e] = fmaf(v.w, w3, acc[e]);
        }
    }
}

// ---------------- node linear ----------------
__global__ void node_lin(const float* __restrict__ h,
                         const float* __restrict__ Wlin,
                         const float* __restrict__ blin) {
    __shared__ __align__(16) float s_in[TN * D];
    int t = threadIdx.x;
    int r0 = blockIdx.x * TN;
    for (int e = 0; e < TN; e++) s_in[e * D + t] = h[(r0 + e) * D + t];
    __syncthreads();
    float acc[TN];
    mlp_layer<TN, 128, 128>(Wlin, s_in, blin[t], acc, t);
#pragma unroll
    for (int e = 0; e < TN; e++) g_hh[(r0 + e) * D + t] = acc[e];
}

// ---------------- edge message + attention (tf32 mma) ----------------
__global__ void __launch_bounds__(128, 5)
edge_msg(const float* __restrict__ x, const int* __restrict__ ei,
         const float* __restrict__ edge_mask,
         const float* __restrict__ edge_attr,
         const float* __restrict__ be1, const float* __restrict__ be2,
         const float* __restrict__ ba1,
         const float* __restrict__ Wa2, const float* __restrict__ ba2) {
    extern __shared__ float sm[];
    float* sA0   = sm;                  // 4224: att-in frags m0 (33 ksteps); reused for M1
    float* sA1   = sA0 + 4224;          // 4224: att-in m1
    float* s_gp  = sA1 + 4224;          // 128: gate partials
    float* s_geo = s_gp + 128;          // 32: geo^2 per edge
    float* s_at  = s_geo + 32;          // 32: att per edge
    float* s_em  = s_at + 32;           // 32
    int*   s_row = (int*)(s_em + 32);   // 32
    int*   s_col = s_row + 32;          // 32

    int t = threadIdx.x, lane = t & 31, w = t >> 5;
    int e0b = blockIdx.x * TE;

    if (t < TE) {
        s_row[t] = ei[e0b + t];
        s_col[t] = ei[NE + e0b + t];
        s_em[t]  = edge_mask[e0b + t];
    }
    __syncthreads();

    // gather: warp w owns edges [w*8, w*8+8), 4 feature passes of 32
#pragma unroll
    for (int i = 0; i < 8; i++) {
        int e = w * 8 + i;
        int r = s_row[e], c = s_col[e];
        float q = 0.f;
#pragma unroll
        for (int pass = 0; pass < 4; pass++) {
            int k = pass * 32 + lane;
            float hr = g_hh[r * D + k];
            float hc = g_hh[c * D + k];
            stp(sA0, sA1, e, k, hr);
            stp(sA0, sA1, e, 128 + k, hc);
            float v = hc - hr;
            q = fmaf(v, v, q);
        }
#pragma unroll
        for (int o = 16; o > 0; o >>= 1) q += __shfl_down_sync(0xffffffffu, q, o);
        if (lane == 0) s_geo[e] = q;
    }
    __syncthreads();

    if (t < TE) {
        int e = t;
        float geo = sqrtf(s_geo[e] + 1e-8f);
        int r = s_row[e], c = s_col[e];
        float dx = x[r * 3 + 0] - x[c * 3 + 0];
        float dy = x[r * 3 + 1] - x[c * 3 + 1];
        float dz = x[r * 3 + 2] - x[c * 3 + 2];
        float dist = sqrtf(dx * dx + dy * dy + dz * dz + 1e-8f);
        float ea = edge_attr[e0b + e];
        stp(sA0, sA1, e, 256, dist);
        stp(sA0, sA1, e, 257, ea);
        stp(sA0, sA1, e, 258, geo);
#pragma unroll
        for (int k = 259; k < 264; k++) stp(sA0, sA1, e, k, 0.f);
        g_e3[(e0b + e) * 3 + 0] = dist;
        g_e3[(e0b + e) * 3 + 1] = ea;
        g_e3[(e0b + e) * 3 + 2] = geo;
    }
    __syncthreads();

    // layer A1: att_in @ Wa1 -> gate partials
    float cA[8][4];
    init_bias(ba1, lane, w, cA);
    gemm2<33>(sA0, sA1, g_Wa1p, lane, w, cA);
    {
        float p0 = 0.f, p1 = 0.f, p2 = 0.f, p3 = 0.f;
#pragma unroll
        for (int j = 0; j < 4; j++) {
            float2 w2 = *(const float2*)(Wa2 + w * 32 + j * 8 + (lane & 3) * 2);
            p0 += siluf(cA[j][0]) * w2.x + siluf(cA[j][1]) * w2.y;
            p1 += siluf(cA[j][2]) * w2.x + siluf(cA[j][3]) * w2.y;
            p2 += siluf(cA[4 + j][0]) * w2.x + siluf(cA[4 + j][1]) * w2.y;
            p3 += siluf(cA[4 + j][2]) * w2.x + siluf(cA[4 + j][3]) * w2.y;
        }
        p0 += __shfl_down_sync(0xffffffffu, p0, 2, 4); p0 += __shfl_down_sync(0xffffffffu, p0, 1, 4);
        p1 += __shfl_down_sync(0xffffffffu, p1, 2, 4); p1 += __shfl_down_sync(0xffffffffu, p1, 1, 4);
        p2 += __shfl_down_sync(0xffffffffu, p2, 2, 4); p2 += __shfl_down_sync(0xffffffffu, p2, 1, 4);
        p3 += __shfl_down_sync(0xffffffffu, p3, 2, 4); p3 += __shfl_down_sync(0xffffffffu, p3, 1, 4);
        if ((lane & 3) == 0) {
            int g = lane >> 2;
            s_gp[g * 4 + w]        = p0;
            s_gp[(g + 8) * 4 + w]  = p1;
            s_gp[(g + 16) * 4 + w] = p2;
            s_gp[(g + 24) * 4 + w] = p3;
        }
    }

    // layer M1 on SAME fragments via fused We1' (= [-We1 | +We1 | We1_e3])
    float cM[8][4];
    init_bias(be1, lane, w, cM);
    gemm2<33>(sA0, sA1, g_We1p, lane, w, cM);
    __syncthreads();  // all warps done reading sA* / writing s_gp

    // write silu(M1) fragment-permuted into sA* (alias); finalize att gate
#pragma unroll
    for (int j = 0; j < 4; j++) {
        int n = w * 32 + j * 8 + (lane & 3) * 2;
        int g = lane >> 2;
#pragma unroll
        for (int m = 0; m < 2; m++) {
            int e = g + m * 16;
            stp(sA0, sA1, e, n, siluf(cM[m * 4 + j][0]));
            stp(sA0, sA1, e, n + 1, siluf(cM[m * 4 + j][1]));
            stp(sA0, sA1, e + 8, n, siluf(cM[m * 4 + j][2]));
            stp(sA0, sA1, e + 8, n + 1, siluf(cM[m * 4 + j][3]));
        }
    }
    if (t < TE) {
        float z = s_gp[t * 4] + s_gp[t * 4 + 1] + s_gp[t * 4 + 2] + s_gp[t * 4 + 3] + ba2[0];
        s_at[t] = s_em[t] / (1.f + expf(-z));
    }
    __syncthreads();

    // layer MSG: M1 @ We2 ; scale by att ; scatter
    float cO[8][4];
    init_bias(be2, lane, w, cO);
    gemm2<16>(sA0, sA1, g_We2p, lane, w, cO);
#pragma unroll
    for (int j = 0; j < 4; j++) {
        int n = w * 32 + j * 8 + (lane & 3) * 2;
        int g = lane >> 2;
#pragma unroll
        for (int m = 0; m < 2; m++) {
            int e = g + m * 16;
            float aL = s_at[e], aH = s_at[e + 8];
            red2(&g_agg[s_row[e] * D + n], cO[m * 4 + j][0] * aL, cO[m * 4 + j][1] * aL);
            red2(&g_agg[s_row[e + 8] * D + n], cO[m * 4 + j][2] * aH, cO[m * 4 + j][3] * aH);
        }
    }
}

// ---------------- node MLP + residual + LN + silu -> d_out ----------------
__global__ void node_mlp(const float* __restrict__ Wn1, const float* __restrict__ bn1,
                         const float* __restrict__ Wn2, const float* __restrict__ bn2,
                         const float* __restrict__ ln_g, const float* __restrict__ ln_b,
                         float* __restrict__ out_h) {
    __shared__ __align__(16) float s_a[TN * 128];
    __shared__ __align__(16) float s_t[TN * 128];
    __shared__ float s_mu[TN], s_rs[TN];
    int t = threadIdx.x, lane = t & 31, wid = t >> 5;
    int r0 = blockIdx.x * TN;

    for (int e = 0; e < TN; e++) s_a[e * 128 + t] = g_agg[(r0 + e) * D + t];
    __syncthreads();

    float acc[TN];
    mlp_layer<TN, 128, 128>(Wn1, s_a, bn1[t], acc, t);
#pragma unroll
    for (int e = 0; e < TN; e++) s_t[e * 128 + t] = siluf(acc[e]);
    __syncthreads();

    mlp_layer<TN, 128, 128>(Wn2, s_t, bn2[t], acc, t);
#pragma unroll
    for (int e = 0; e < TN; e++) {
        float v = g_hh[(r0 + e) * D + t] + acc[e];
        s_a[e * 128 + t] = v;
    }
    __syncthreads();

    for (int i = 0; i < TN / 4; i++) {
        int e = wid * (TN / 4) + i;
        float v0 = s_a[e * 128 + lane];
        float v1 = s_a[e * 128 + lane + 32];
        float v2 = s_a[e * 128 + lane + 64];
        float v3 = s_a[e * 128 + lane + 96];
        float s = v0 + v1 + v2 + v3;
        float q = v0 * v0 + v1 * v1 + v2 * v2 + v3 * v3;
#pragma unroll
        for (int o = 16; o > 0; o >>= 1) {
            s += __shfl_down_sync(0xffffffffu, s, o);
            q += __shfl_down_sync(0xffffffffu, q, o);
        }
        if (lane == 0) {
            float mu = s * (1.f / 128.f);
            float var = q * (1.f / 128.f) - mu * mu;
            s_mu[e] = mu;
            s_rs[e] = rsqrtf(var + 1e-5f);
        }
    }
    __syncthreads();

    float g = ln_g[t], bb = ln_b[t];
    for (int e = 0; e < TN; e++) {
        float v = (s_a[e * 128 + t] - s_mu[e]) * s_rs[e] * g + bb;
        out_h[(r0 + e) * D + t] = siluf(v);
    }
}

// ---------------- coord MLP + scatter (tf32 mma) ----------------
__global__ void __launch_bounds__(128, 5)
edge_coord(const float* __restrict__ x, const int* __restrict__ ei,
           const float* __restrict__ edge_mask,
           const float* __restrict__ hh2,
           const float* __restrict__ bc1, const float* __restrict__ bc2,
           const float* __restrict__ Wc3) {
    extern __shared__ float sm[];
    float* sA0   = sm;                  // 4224 (33 ksteps); reused for M1
    float* sA1   = sA0 + 4224;          // 4224
    float* s_gp  = sA1 + 4224;          // 128
    float* s_em  = s_gp + 128;          // 32
    float* s_d   = s_em + 32;           // 32 dist
    int*   s_row = (int*)(s_d + 32);
    int*   s_col = s_row + 32;

    int t = threadIdx.x, lane = t & 31, w = t >> 5;
    int e0b = blockIdx.x * TE;

    if (t < TE) {
        s_row[t] = ei[e0b + t];
        s_col[t] = ei[NE + e0b + t];
        s_em[t]  = edge_mask[e0b + t];
    }
    __syncthreads();

    // gather: warp w owns edges [w*8, w*8+8)
#pragma unroll
    for (int i = 0; i < 8; i++) {
        int e = w * 8 + i;
        int r = s_row[e], c = s_col[e];
#pragma unroll
        for (int pass = 0; pass < 4; pass++) {
            int k = pass * 32 + lane;
            stp(sA0, sA1, e, k, hh2[r * D + k]);
            stp(sA0, sA1, e, 128 + k, hh2[c * D + k]);
        }
    }
    if (t < TE) {
        int e = t;
        float dist = g_e3[(e0b + e) * 3 + 0];
        float ea   = g_e3[(e0b + e) * 3 + 1];
        float geo  = g_e3[(e0b + e) * 3 + 2];
        stp(sA0, sA1, e, 256, dist);
        stp(sA0, sA1, e, 257, ea);
        stp(sA0, sA1, e, 258, geo);
#pragma unroll
        for (int k = 259; k < 264; k++) stp(sA0, sA1, e, k, 0.f);
        s_d[e] = dist;
    }
    __syncthreads();

    float c1[8][4];
    init_bias(bc1, lane, w, c1);
    gemm2<33>(sA0, sA1, g_Wc1p, lane, w, c1);
    __syncthreads();  // everyone done reading sA*

#pragma unroll
    for (int j = 0; j < 4; j++) {
        int n = w * 32 + j * 8 + (lane & 3) * 2;
        int g = lane >> 2;
#pragma unroll
        for (int m = 0; m < 2; m++) {
            int e = g + m * 16;
            stp(sA0, sA1, e, n, siluf(c1[m * 4 + j][0]));
            stp(sA0, sA1, e, n + 1, siluf(c1[m * 4 + j][1]));
            stp(sA0, sA1, e + 8, n, siluf(c1[m * 4 + j][2]));
            stp(sA0, sA1, e + 8, n + 1, siluf(c1[m * 4 + j][3]));
        }
    }
    __syncthreads();

    float c2[8][4];
    init_bias(bc2, lane, w, c2);
    gemm2<16>(sA0, sA1, g_Wc2p, lane, w, c2);

    // m = silu(M2) @ Wc3 via fragment reduction
    {
        float p0 = 0.f, p1 = 0.f, p2 = 0.f, p3 = 0.f;
#pragma unroll
        for (int j = 0; j < 4; j++) {
            float2 w3 = *(const float2*)(Wc3 + w * 32 + j * 8 + (lane & 3) * 2);
            p0 += siluf(c2[j][0]) * w3.x + siluf(c2[j][1]) * w3.y;
            p1 += siluf(c2[j][2]) * w3.x + siluf(c2[j][3]) * w3.y;
            p2 += siluf(c2[4 + j][0]) * w3.x + siluf(c2[4 + j][1]) * w3.y;
            p3 += siluf(c2[4 + j][2]) * w3.x + siluf(c2[4 + j][3]) * w3.y;
        }
        p0 += __shfl_down_sync(0xffffffffu, p0, 2, 4); p0 += __shfl_down_sync(0xffffffffu, p0, 1, 4);
        p1 += __shfl_down_sync(0xffffffffu, p1, 2, 4); p1 += __shfl_down_sync(0xffffffffu, p1, 1, 4);
        p2 += __shfl_down_sync(0xffffffffu, p2, 2, 4); p2 += __shfl_down_sync(0xffffffffu, p2, 1, 4);
        p3 += __shfl_down_sync(0xffffffffu, p3, 2, 4); p3 += __shfl_down_sync(0xffffffffu, p3, 1, 4);
        if ((lane & 3) == 0) {
            int g = lane >> 2;
            s_gp[g * 4 + w]        = p0;
            s_gp[(g + 8) * 4 + w]  = p1;
            s_gp[(g + 16) * 4 + w] = p2;
            s_gp[(g + 24) * 4 + w] = p3;
        }
    }
    __syncthreads();

    if (t < TE) {
        int e = t;
        float mval = (s_gp[e * 4] + s_gp[e * 4 + 1] + s_gp[e * 4 + 2] + s_gp[e * 4 + 3])
                     * s_em[e];
        int r = s_row[e], c = s_col[e];
        float dx = x[r * 3 + 0] - x[c * 3 + 0];
        float dy = x[r * 3 + 1] - x[c * 3 + 1];
        float dz = x[r * 3 + 2] - x[c * 3 + 2];
        float inv = 1.f / (s_d[e] + 1.f);
        atomicAdd(&g_aggx[r * 3 + 0], dx * inv * mval);
        atomicAdd(&g_aggx[r * 3 + 1], dy * inv * mval);
        atomicAdd(&g_aggx[r * 3 + 2], dz * inv * mval);
    }
}

__global__ void finalize_x(const float* __restrict__ x,
                           const float* __restrict__ node_mask,
                           float* __restrict__ out) {
    int i = blockIdx.x * blockDim.x + threadIdx.x;
    if (i < NN * 3) {
        out[i] = (x[i] + g_aggx[i] * (1.f / 100.f)) * node_mask[i / 3];
    }
}

// ---------------- launcher ----------------
extern "C" void kernel_launch(void* const* d_in, const int* in_sizes, int n_in,
                              void* d_out, int out_size) {
    const float* h         = (const float*)d_in[0];
    const float* x         = (const float*)d_in[1];
    const int*   ei        = (const int*)d_in[2];
    const float* node_mask = (const float*)d_in[3];
    const float* edge_mask = (const float*)d_in[4];
    const float* edge_attr = (const float*)d_in[5];
    const float* Wlin = (const float*)d_in[6];
    const float* blin = (const float*)d_in[7];
    const float* We1  = (const float*)d_in[8];
    const float* be1  = (const float*)d_in[9];
    const float* We2  = (const float*)d_in[10];
    const float* be2  = (const float*)d_in[11];
    const float* Wn1  = (const float*)d_in[12];
    const float* bn1  = (const float*)d_in[13];
    const float* Wn2  = (const float*)d_in[14];
    const float* bn2  = (const float*)d_in[15];
    const float* Wa1  = (const float*)d_in[16];
    const float* ba1  = (const float*)d_in[17];
    const float* Wa2  = (const float*)d_in[18];
    const float* ba2  = (const float*)d_in[19];
    const float* ln_g = (const float*)d_in[20];
    const float* ln_b = (const float*)d_in[21];
    const float* Wc1  = (const float*)d_in[22];
    const float* bc1  = (const float*)d_in[23];
    const float* Wc2  = (const float*)d_in[24];
    const float* bc2  = (const float*)d_in[25];
    const float* Wc3  = (const float*)d_in[26];
    float* out = (float*)d_out;

    const int SMEM_MSG = (4224 + 4224 + 128 + 32 + 32 + 32) * 4 + 2 * 32 * 4;
    const int SMEM_CRD = (4224 + 4224 + 128 + 32 + 32) * 4 + 2 * 32 * 4;

    cudaFuncSetAttribute(edge_msg, cudaFuncAttributeMaxDynamicSharedMemorySize, SMEM_MSG);
    cudaFuncSetAttribute(edge_coord, cudaFuncAttributeMaxDynamicSharedMemorySize, SMEM_CRD);

    prep_weights<<<dim3(66, 5), 256>>>(Wa1, We1, We2, Wc1, Wc2);
    zero_scratch<<<1024, 256>>>();
    node_lin<<<NN / TN, 128>>>(h, Wlin, blin);
    edge_msg<<<NE / TE, 128, SMEM_MSG>>>(x, ei, edge_mask, edge_attr,
                                         be1, be2, ba1, Wa2, ba2);
    node_mlp<<<NN / TN, 128>>>(Wn1, bn1, Wn2, bn2, ln_g, ln_b, out);
    edge_coord<<<NE / TE, 128, SMEM_CRD>>>(x, ei, edge_mask, out, bc1, bc2, Wc3);
    finalize_x<<<(NN * 3 + 255) / 256, 256>>>(x, node_mask, out + NN * D);
}